// round 13
// baseline (speedup 1.0000x reference)
#include <cuda_runtime.h>
#include <cuda_fp16.h>
#include <cstdint>

#define TSEQ 2048
#define CEMB 1024

// ---------------- scratch ----------------
__device__ __align__(128) __half g_E[134217728];     // [2,16,2048,2048] exp(S-8) fp16
__device__ __align__(128) float  g_rowsum[65536];    // [2,16,2048] fp32 sums
__device__ __align__(128) __half g_invsum[65536];    // 1/rowsum fp16
__device__ __align__(128) __half g_xh[4194304];      // [4096,1024] x hi
__device__ __align__(128) __half g_xl[4194304];      // x lo (scores A only)
__device__ __align__(128) __half g_wth[16777216];    // Wt[h][n][k] fp16
__device__ __align__(128) __half g_Zh[67108864];     // [16][4096 r][1024 c] fp16

// ---------------- low-level helpers ----------------
__device__ __forceinline__ uint32_t smem_u32(const void* p) {
    uint32_t a;
    asm("{ .reg .u64 t; cvta.to.shared.u64 t, %1; cvt.u32.u64 %0, t; }" : "=r"(a) : "l"(p));
    return a;
}
__device__ __forceinline__ void cp16(uint32_t dst, const void* src) {
    asm volatile("cp.async.cg.shared.global [%0], [%1], 16;" :: "r"(dst), "l"(src));
}
__device__ __forceinline__ void cp_commit() { asm volatile("cp.async.commit_group;" ::: "memory"); }
template <int N> __device__ __forceinline__ void cp_wait() {
    asm volatile("cp.async.wait_group %0;" :: "n"(N) : "memory");
}
__device__ __forceinline__ void ldmx4(uint32_t r[4], uint32_t a) {
    asm volatile("ldmatrix.sync.aligned.m8n8.x4.shared.b16 {%0,%1,%2,%3}, [%4];"
                 : "=r"(r[0]), "=r"(r[1]), "=r"(r[2]), "=r"(r[3]) : "r"(a));
}
__device__ __forceinline__ void ldmx4t(uint32_t r[4], uint32_t a) {
    asm volatile("ldmatrix.sync.aligned.m8n8.x4.trans.shared.b16 {%0,%1,%2,%3}, [%4];"
                 : "=r"(r[0]), "=r"(r[1]), "=r"(r[2]), "=r"(r[3]) : "r"(a));
}
__device__ __forceinline__ void mma16816(float* c, const uint32_t* a, const uint32_t* b) {
    asm volatile(
        "mma.sync.aligned.m16n8k16.row.col.f32.f16.f16.f32 "
        "{%0,%1,%2,%3}, {%4,%5,%6,%7}, {%8,%9}, {%0,%1,%2,%3};"
        : "+f"(c[0]), "+f"(c[1]), "+f"(c[2]), "+f"(c[3])
        : "r"(a[0]), "r"(a[1]), "r"(a[2]), "r"(a[3]), "r"(b[0]), "r"(b[1]));
}
__device__ __forceinline__ uint32_t hmul2u(uint32_t a, uint32_t b) {
    uint32_t d;
    asm("mul.f16x2 %0, %1, %2;" : "=r"(d) : "r"(a), "r"(b));
    return d;
}
__device__ __forceinline__ void split_f16(float v, __half& hi, __half& lo) {
    hi = __float2half_rn(v);
    lo = __float2half_rn(v - __half2float(hi));
}
__device__ __forceinline__ uint32_t pack2h(__half a, __half b) {
    union { __half h[2]; uint32_t u; } v; v.h[0] = a; v.h[1] = b; return v.u;
}
__device__ __forceinline__ uint32_t dup_h(__half a) {
    union { __half h[2]; uint32_t u; } v; v.h[0] = a; v.h[1] = a; return v.u;
}

// ---------------- smem layouts (CTA tile 128 x 256, K=32 sub-tile) ----------------
#define A_LO     10240u
#define SC_BOFF  20480u
#define STAGE_SC 40960u
#define ZO_BOFF  10240u
#define SUB_Z    30720u
#define PAIR_Z   61440u
#define SUB_O    27136u
#define QUAD_O   108544u
#define SMEM_SC  (2 * STAGE_SC)
#define SMEM_Z   (3 * PAIR_Z)
#define SMEM_O   (2 * QUAD_O)

// A hi+lo (scores)
__device__ __forceinline__ void copyA2(uint32_t sb, const __half* hi,
                                       const __half* lo, int ld, int tid) {
#pragma unroll
    for (int i = 0; i < 2; ++i) {
        const int idx = tid + i * 256;
        const int r = idx >> 2, c = idx & 3;
        const uint32_t d = sb + (uint32_t)r * 80u + (uint32_t)c * 16u;
        const size_t g = (size_t)r * ld + c * 8;
        cp16(d, hi + g);
        cp16(d + A_LO, lo + g);
    }
}
// A single
__device__ __forceinline__ void copyA1(uint32_t sb, const __half* hi, int ld, int tid) {
#pragma unroll
    for (int i = 0; i < 2; ++i) {
        const int idx = tid + i * 256;
        const int r = idx >> 2, c = idx & 3;
        cp16(sb + (uint32_t)r * 80u + (uint32_t)c * 16u, hi + (size_t)r * ld + c * 8);
    }
}
// B single K-major (256 rows x 32)
__device__ __forceinline__ void copyB1(uint32_t dst, const __half* hi, int ld, int tid) {
#pragma unroll
    for (int i = 0; i < 4; ++i) {
        const int idx = tid + i * 256;
        const int r = idx >> 2, c = idx & 3;
        cp16(dst + (uint32_t)r * 80u + (uint32_t)c * 16u, hi + (size_t)r * ld + c * 8);
    }
}
// B single S-major (32 k-rows x 256 cols, pitch 528B)
__device__ __forceinline__ void copyBS1(uint32_t dst, const __half* hi, int ld, int tid) {
#pragma unroll
    for (int i = 0; i < 4; ++i) {
        const int idx = tid + i * 256;
        const int r = idx >> 5, c = idx & 31;
        cp16(dst + (uint32_t)r * 528u + (uint32_t)c * 16u, hi + (size_t)r * ld + c * 8);
    }
}

// ---------------- compute: 64x64 warp tile ----------------
// 2-product (scores): (Ah + Al) x Bh, K-major B
__device__ __forceinline__ void compute2k(uint32_t sb, int wm, int wn, int lane,
                                          float (&acc)[4][8][4]) {
#pragma unroll
    for (int ks = 0; ks < 2; ++ks) {
        const int k0 = ks * 16;
        uint32_t Ah[4][4], Al[4][4], Bh[4][4];
#pragma unroll
        for (int mt = 0; mt < 4; ++mt) {
            const uint32_t ad = sb + (uint32_t)(wm + mt * 16 + (lane & 15)) * 80u +
                                (uint32_t)(k0 + (lane >> 4) * 8) * 2u;
            ldmx4(Ah[mt], ad);
            ldmx4(Al[mt], ad + A_LO);
        }
#pragma unroll
        for (int np = 0; np < 4; ++np) {
            const uint32_t ad = sb + SC_BOFF +
                (uint32_t)(wn + np * 16 + (lane & 7) + (lane >> 4) * 8) * 80u +
                (uint32_t)(k0 + ((lane >> 3) & 1) * 8) * 2u;
            ldmx4(Bh[np], ad);
        }
#pragma unroll
        for (int mt = 0; mt < 4; ++mt)
#pragma unroll
            for (int nt = 0; nt < 8; ++nt) {
                const uint32_t* bh = &Bh[nt >> 1][(nt & 1) * 2];
                mma16816(acc[mt][nt], Ah[mt], bh);
                mma16816(acc[mt][nt], Al[mt], bh);
            }
    }
}
// single product (z): A(h) x B(h) K-major
__device__ __forceinline__ void compute1k(uint32_t sb, int wm, int wn, int lane,
                                          float (&acc)[4][8][4]) {
#pragma unroll
    for (int ks = 0; ks < 2; ++ks) {
        const int k0 = ks * 16;
        uint32_t Ah[4][4], Bh[4][4];
#pragma unroll
        for (int mt = 0; mt < 4; ++mt) {
            const uint32_t ad = sb + (uint32_t)(wm + mt * 16 + (lane & 15)) * 80u +
                                (uint32_t)(k0 + (lane >> 4) * 8) * 2u;
            ldmx4(Ah[mt], ad);
        }
#pragma unroll
        for (int np = 0; np < 4; ++np) {
            const uint32_t ad = sb + ZO_BOFF +
                (uint32_t)(wn + np * 16 + (lane & 7) + (lane >> 4) * 8) * 80u +
                (uint32_t)(k0 + ((lane >> 3) & 1) * 8) * 2u;
            ldmx4(Bh[np], ad);
        }
#pragma unroll
        for (int mt = 0; mt < 4; ++mt)
#pragma unroll
            for (int nt = 0; nt < 8; ++nt)
                mma16816(acc[mt][nt], Ah[mt], &Bh[nt >> 1][(nt & 1) * 2]);
    }
}
// single product with per-row A scaling (out): A(h)*sc x B(h) S-major
__device__ __forceinline__ void compute1s(uint32_t sb, int wm, int wn, int lane,
                                          const uint32_t (&sc)[4][2],
                                          float (&acc)[4][8][4]) {
#pragma unroll
    for (int ks = 0; ks < 2; ++ks) {
        const int k0 = ks * 16;
        uint32_t Ah[4][4], Bh[4][4];
#pragma unroll
        for (int mt = 0; mt < 4; ++mt) {
            const uint32_t ad = sb + (uint32_t)(wm + mt * 16 + (lane & 15)) * 80u +
                                (uint32_t)(k0 + (lane >> 4) * 8) * 2u;
            ldmx4(Ah[mt], ad);
            Ah[mt][0] = hmul2u(Ah[mt][0], sc[mt][0]);   // row g,   k lo
            Ah[mt][1] = hmul2u(Ah[mt][1], sc[mt][1]);   // row g+8, k lo
            Ah[mt][2] = hmul2u(Ah[mt][2], sc[mt][0]);   // row g,   k hi
            Ah[mt][3] = hmul2u(Ah[mt][3], sc[mt][1]);   // row g+8, k hi
        }
#pragma unroll
        for (int np = 0; np < 4; ++np) {
            const uint32_t ad = sb + ZO_BOFF +
                (uint32_t)(k0 + (lane & 7) + ((lane >> 3) & 1) * 8) * 528u +
                (uint32_t)(wn + np * 16 + (lane >> 4) * 8) * 2u;
            ldmx4t(Bh[np], ad);
        }
#pragma unroll
        for (int mt = 0; mt < 4; ++mt)
#pragma unroll
            for (int nt = 0; nt < 8; ++nt)
                mma16816(acc[mt][nt], Ah[mt], &Bh[nt >> 1][(nt & 1) * 2]);
    }
}

// warps: 2 (rows) x 4 (cols) -> CTA 128 x 256
#define GEMM_PRE()                                                   \
    extern __shared__ char smraw[];                                  \
    const uint32_t sb = smem_u32(smraw);                             \
    const int tid = threadIdx.x, lane = tid & 31, warp = tid >> 5;   \
    const int wm = (warp & 1) * 64, wn = (warp >> 1) * 64;           \
    float acc[4][8][4];                                              \
    _Pragma("unroll") for (int i = 0; i < 4; ++i)                    \
    _Pragma("unroll") for (int j = 0; j < 8; ++j)                    \
    _Pragma("unroll") for (int q = 0; q < 4; ++q) acc[i][j][q] = 0.f;

// ---------------- aux kernels ----------------
__global__ __launch_bounds__(256) void zero_kernel() {
    g_rowsum[blockIdx.x * 256 + threadIdx.x] = 0.f;
}
__global__ __launch_bounds__(256) void inv_kernel() {
    const int i = blockIdx.x * 256 + threadIdx.x;
    g_invsum[i] = __float2half_rn(1.0f / g_rowsum[i]);
}

__global__ __launch_bounds__(256) void xsplit_kernel(const float* __restrict__ x) {
    const size_t i = (size_t)blockIdx.x * 256 + threadIdx.x;
    float4 v = *(const float4*)(x + i * 4);
    union { __half a[4]; uint2 u; } H, L;
    split_f16(v.x, H.a[0], L.a[0]); split_f16(v.y, H.a[1], L.a[1]);
    split_f16(v.z, H.a[2], L.a[2]); split_f16(v.w, H.a[3], L.a[3]);
    *(uint2*)(g_xh + i * 4) = H.u;
    *(uint2*)(g_xl + i * 4) = L.u;
}

__global__ __launch_bounds__(256) void wsplit_kernel(const float* __restrict__ wt) {
    __shared__ float tile[32][33];
    const int h = blockIdx.z, k0 = blockIdx.y * 32, n0 = blockIdx.x * 32;
    const int tx = threadIdx.x, ty = threadIdx.y;
#pragma unroll
    for (int j = 0; j < 4; ++j)
        tile[ty + 8 * j][tx] = wt[((size_t)h * 1024 + k0 + ty + 8 * j) * 1024 + n0 + tx];
    __syncthreads();
#pragma unroll
    for (int j = 0; j < 4; ++j) {
        const int nn = ty + 8 * j, kk = tx;
        g_wth[((size_t)h * 1024 + n0 + nn) * 1024 + k0 + kk] =
            __float2half_rn(tile[kk][nn]);
    }
}

// ---------------- scores: E = exp(y.yT/8 - 8), rowsum accumulation ----------------
__global__ __launch_bounds__(256, 1) void scores_hmma() {
    GEMM_PRE();
    __shared__ float rsum[128];
    const int bh = blockIdx.z, b = bh >> 4, hh = bh & 15;
    const int row0 = blockIdx.y * 128, col0 = blockIdx.x * 256;

    const size_t ab = (size_t)(b * TSEQ + row0) * CEMB + hh * 64;
    const size_t bb = (size_t)(b * TSEQ + col0) * CEMB + hh * 64;

    copyA2(sb, g_xh + ab, g_xl + ab, CEMB, tid);
    copyB1(sb + SC_BOFF, g_xh + bb, CEMB, tid);
    cp_commit();
    copyA2(sb + STAGE_SC, g_xh + ab + 32, g_xl + ab + 32, CEMB, tid);
    copyB1(sb + STAGE_SC + SC_BOFF, g_xh + bb + 32, CEMB, tid);
    cp_commit();
    if (tid < 128) rsum[tid] = 0.f;
#pragma unroll
    for (int kt = 0; kt < 2; ++kt) {
        if (kt == 0) cp_wait<1>(); else cp_wait<0>();
        __syncthreads();
        compute2k(sb + kt * STAGE_SC, wm, wn, lane, acc);
        __syncthreads();
    }

    const int g = lane >> 2, t2 = (lane & 3) * 2;
    __half* Ep = g_E + ((size_t)bh * TSEQ + row0) * TSEQ + col0;
    float rs[4][2];
#pragma unroll
    for (int mt = 0; mt < 4; ++mt) { rs[mt][0] = 0.f; rs[mt][1] = 0.f; }
#pragma unroll
    for (int mt = 0; mt < 4; ++mt)
#pragma unroll
        for (int nt = 0; nt < 8; ++nt) {
            const int r = wm + mt * 16 + g, c = wn + nt * 8 + t2;
            const float e0 = __expf(acc[mt][nt][0] * 0.125f - 8.0f);
            const float e1 = __expf(acc[mt][nt][1] * 0.125f - 8.0f);
            const float e2 = __expf(acc[mt][nt][2] * 0.125f - 8.0f);
            const float e3 = __expf(acc[mt][nt][3] * 0.125f - 8.0f);
            rs[mt][0] += e0 + e1;
            rs[mt][1] += e2 + e3;
            *(uint32_t*)(Ep + (size_t)r * TSEQ + c) =
                pack2h(__float2half_rn(e0), __float2half_rn(e1));
            *(uint32_t*)(Ep + (size_t)(r + 8) * TSEQ + c) =
                pack2h(__float2half_rn(e2), __float2half_rn(e3));
        }
#pragma unroll
    for (int mt = 0; mt < 4; ++mt) {
        atomicAdd(&rsum[wm + mt * 16 + g], rs[mt][0]);
        atomicAdd(&rsum[wm + mt * 16 + g + 8], rs[mt][1]);
    }
    __syncthreads();
    if (tid < 128)
        atomicAdd(&g_rowsum[(size_t)bh * TSEQ + row0 + tid], rsum[tid]);
}

// ---------------- Z[h] = X @ W_h (K=1024), paired k-chunks, 3 pair-stages ----------------
__global__ __launch_bounds__(256, 1) void z_hmma() {
    GEMM_PRE();
    const int hh = blockIdx.z;
    const int row0 = blockIdx.y * 128, col0 = blockIdx.x * 256;

    const size_t ab = (size_t)row0 * CEMB;
    const size_t bb = ((size_t)hh * 1024 + col0) * 1024;
    const int NP = 16;

    auto loadP = [&](int t) {
        const uint32_t st = sb + (uint32_t)(t % 3) * PAIR_Z;
        copyA1(st, g_xh + ab + (2 * t) * 32, CEMB, tid);
        copyB1(st + ZO_BOFF, g_wth + bb + (2 * t) * 32, 1024, tid);
        copyA1(st + SUB_Z, g_xh + ab + (2 * t + 1) * 32, CEMB, tid);
        copyB1(st + SUB_Z + ZO_BOFF, g_wth + bb + (2 * t + 1) * 32, 1024, tid);
    };
    loadP(0); cp_commit();
    loadP(1); cp_commit();
    for (int pt = 0; pt < NP; ++pt) {
        cp_wait<1>();
        __syncthreads();
        if (pt + 2 < NP) loadP(pt + 2);
        cp_commit();
        const uint32_t st = sb + (uint32_t)(pt % 3) * PAIR_Z;
        compute1k(st, wm, wn, lane, acc);
        compute1k(st + SUB_Z, wm, wn, lane, acc);
    }

    const int g = lane >> 2, t2 = (lane & 3) * 2;
#pragma unroll
    for (int mt = 0; mt < 4; ++mt)
#pragma unroll
        for (int nt = 0; nt < 8; ++nt) {
            const int r = row0 + wm + mt * 16 + g;
            const int c = col0 + wn + nt * 8 + t2;
            const size_t o0 = ((size_t)hh * 4096 + r) * 1024 + c;
            *(uint32_t*)(g_Zh + o0) =
                pack2h(__float2half_rn(acc[mt][nt][0]), __float2half_rn(acc[mt][nt][1]));
            *(uint32_t*)(g_Zh + o0 + 8 * 1024) =
                pack2h(__float2half_rn(acc[mt][nt][2]), __float2half_rn(acc[mt][nt][3]));
        }
}

// ---------------- out[b] = sum_h (E_h * invsum) @ Z[h,b], quad k-chunks ----------------
__global__ __launch_bounds__(256, 1) void out_hmma(float* __restrict__ out) {
    GEMM_PRE();
    const int b = blockIdx.z;
    const int row0 = blockIdx.y * 128, col0 = blockIdx.x * 256;
    const int g = lane >> 2;

    const size_t arow = ((size_t)(b * 16) * TSEQ + row0) * TSEQ;
    const int NQ = 256;                          // 256 quads of k32 = K 32768 ; head = qt>>4
    auto loadQ = [&](int t) {
        const uint32_t st = sb + (uint32_t)(t & 1) * QUAD_O;
#pragma unroll
        for (int j = 0; j < 4; ++j) {
            const int u = 4 * t + j;
            const int hh = u >> 6, s0 = (u & 63) * 32;
            const size_t ap = arow + (size_t)hh * TSEQ * TSEQ + s0;
            const size_t bp = ((size_t)hh * 4096 + b * TSEQ + s0) * 1024 + col0;
            const uint32_t ss = st + (uint32_t)j * SUB_O;
            copyA1(ss, g_E + ap, TSEQ, tid);
            copyBS1(ss + ZO_BOFF, g_Zh + bp, 1024, tid);
        }
    };
    loadQ(0); cp_commit();
    uint32_t sc[4][2];
    int curh = -1;
    for (int qt = 0; qt < NQ; ++qt) {
        const int hh = qt >> 4;
        if (hh != curh) {
            curh = hh;
            const __half* isp = g_invsum + ((size_t)(b * 16 + hh)) * TSEQ + row0;
#pragma unroll
            for (int mt = 0; mt < 4; ++mt) {
                const int r = wm + mt * 16 + g;
                sc[mt][0] = dup_h(isp[r]);
                sc[mt][1] = dup_h(isp[r + 8]);
            }
        }
        cp_wait<0>();
        __syncthreads();
        if (qt + 1 < NQ) loadQ(qt + 1);
        cp_commit();
        const uint32_t st = sb + (uint32_t)(qt & 1) * QUAD_O;
        compute1s(st, wm, wn, lane, sc, acc);
        compute1s(st + SUB_O, wm, wn, lane, sc, acc);
        compute1s(st + 2 * SUB_O, wm, wn, lane, sc, acc);
        compute1s(st + 3 * SUB_O, wm, wn, lane, sc, acc);
    }

    const int t2 = (lane & 3) * 2;
    float* Op = out + ((size_t)(b * TSEQ + row0)) * CEMB + col0;
#pragma unroll
    for (int mt = 0; mt < 4; ++mt)
#pragma unroll
        for (int nt = 0; nt < 8; ++nt) {
            const int r = wm + mt * 16 + g, c = wn + nt * 8 + t2;
            *(float2*)(Op + (size_t)r * CEMB + c) = make_float2(acc[mt][nt][0], acc[mt][nt][1]);
            *(float2*)(Op + (size_t)(r + 8) * CEMB + c) = make_float2(acc[mt][nt][2], acc[mt][nt][3]);
        }
}

// ---------------------------------------------------------------------------
extern "C" void kernel_launch(void* const* d_in, const int* in_sizes, int n_in,
                              void* d_out, int out_size) {
    const float* x  = (const float*)d_in[0];   // [2,2048,1024]
    const float* wt = (const float*)d_in[1];   // [16384,1024]
    float* out = (float*)d_out;

    cudaFuncSetAttribute(scores_hmma, cudaFuncAttributeMaxDynamicSharedMemorySize, SMEM_SC);
    cudaFuncSetAttribute(z_hmma,      cudaFuncAttributeMaxDynamicSharedMemorySize, SMEM_Z);
    cudaFuncSetAttribute(out_hmma,    cudaFuncAttributeMaxDynamicSharedMemorySize, SMEM_O);

    zero_kernel<<<256, 256>>>();
    xsplit_kernel<<<4096, 256>>>(x);
    wsplit_kernel<<<dim3(32, 32, 16), dim3(32, 8)>>>(wt);
    scores_hmma<<<dim3(8, 16, 32), 256, SMEM_SC>>>();
    inv_kernel<<<256, 256>>>();
    z_hmma<<<dim3(4, 32, 16), 256, SMEM_Z>>>();
    out_hmma<<<dim3(4, 16, 2), 256, SMEM_O>>>(out);
}

// round 14
// speedup vs baseline: 1.0387x; 1.0387x over previous
#include <cuda_runtime.h>
#include <cuda_fp16.h>
#include <cstdint>

#define TSEQ 2048
#define CEMB 1024

// ---------------- scratch ----------------
__device__ __align__(128) __half g_E[134217728];     // [2,16,2048,2048] exp(S-8) fp16
__device__ __align__(128) float  g_rowsum[65536];    // [2,16,2048] fp32 sums
__device__ __align__(128) float  g_invf[65536];      // 1/rowsum fp32
__device__ __align__(128) __half g_xh[4194304];      // [4096,1024] x hi
__device__ __align__(128) __half g_xl[4194304];      // x lo (scores A only)
__device__ __align__(128) __half g_wth[16777216];    // Wt[h][n][k] fp16
__device__ __align__(128) __half g_Zh[67108864];     // [16][4096 r][1024 c] fp16

// ---------------- low-level helpers ----------------
__device__ __forceinline__ uint32_t smem_u32(const void* p) {
    uint32_t a;
    asm("{ .reg .u64 t; cvta.to.shared.u64 t, %1; cvt.u32.u64 %0, t; }" : "=r"(a) : "l"(p));
    return a;
}
__device__ __forceinline__ void cp16(uint32_t dst, const void* src) {
    asm volatile("cp.async.cg.shared.global [%0], [%1], 16;" :: "r"(dst), "l"(src));
}
__device__ __forceinline__ void cp_commit() { asm volatile("cp.async.commit_group;" ::: "memory"); }
template <int N> __device__ __forceinline__ void cp_wait() {
    asm volatile("cp.async.wait_group %0;" :: "n"(N) : "memory");
}
__device__ __forceinline__ void ldmx4(uint32_t r[4], uint32_t a) {
    asm volatile("ldmatrix.sync.aligned.m8n8.x4.shared.b16 {%0,%1,%2,%3}, [%4];"
                 : "=r"(r[0]), "=r"(r[1]), "=r"(r[2]), "=r"(r[3]) : "r"(a));
}
__device__ __forceinline__ void ldmx4t(uint32_t r[4], uint32_t a) {
    asm volatile("ldmatrix.sync.aligned.m8n8.x4.trans.shared.b16 {%0,%1,%2,%3}, [%4];"
                 : "=r"(r[0]), "=r"(r[1]), "=r"(r[2]), "=r"(r[3]) : "r"(a));
}
__device__ __forceinline__ void mma16816(float* c, const uint32_t* a, const uint32_t* b) {
    asm volatile(
        "mma.sync.aligned.m16n8k16.row.col.f32.f16.f16.f32 "
        "{%0,%1,%2,%3}, {%4,%5,%6,%7}, {%8,%9}, {%0,%1,%2,%3};"
        : "+f"(c[0]), "+f"(c[1]), "+f"(c[2]), "+f"(c[3])
        : "r"(a[0]), "r"(a[1]), "r"(a[2]), "r"(a[3]), "r"(b[0]), "r"(b[1]));
}
__device__ __forceinline__ void split_f16(float v, __half& hi, __half& lo) {
    hi = __float2half_rn(v);
    lo = __float2half_rn(v - __half2float(hi));
}
__device__ __forceinline__ uint32_t pack2h(__half a, __half b) {
    union { __half h[2]; uint32_t u; } v; v.h[0] = a; v.h[1] = b; return v.u;
}

// ---------------- smem layouts ----------------
// scores (128x128 tile): A(hi)@0, A(lo)@10240, B@20480 : STAGE_SC = 30720, 2 stages
// z (128x256): sub = A@0 + BK@10240 : SUB_Z = 30720 ; pair ; 3 pairs
// out (128x256): sub = A@0 + BS@10240 : SUB_O = 27136 ; quad ; 2 quads
#define A_LO     10240u
#define SC_BOFF  20480u
#define STAGE_SC 30720u
#define ZO_BOFF  10240u
#define SUB_Z    30720u
#define PAIR_Z   61440u
#define SUB_O    27136u
#define QUAD_O   108544u
#define SMEM_SC  (2 * STAGE_SC)
#define SMEM_Z   (3 * PAIR_Z)
#define SMEM_O   (2 * QUAD_O)

// A hi+lo (scores): 128 rows x 32
__device__ __forceinline__ void copyA2(uint32_t sb, const __half* hi,
                                       const __half* lo, int ld, int tid) {
#pragma unroll
    for (int i = 0; i < 2; ++i) {
        const int idx = tid + i * 256;
        const int r = idx >> 2, c = idx & 3;
        const uint32_t d = sb + (uint32_t)r * 80u + (uint32_t)c * 16u;
        const size_t g = (size_t)r * ld + c * 8;
        cp16(d, hi + g);
        cp16(d + A_LO, lo + g);
    }
}
// single K-major 128 rows x 32
__device__ __forceinline__ void copy128(uint32_t dst, const __half* hi, int ld, int tid) {
#pragma unroll
    for (int i = 0; i < 2; ++i) {
        const int idx = tid + i * 256;
        const int r = idx >> 2, c = idx & 3;
        cp16(dst + (uint32_t)r * 80u + (uint32_t)c * 16u, hi + (size_t)r * ld + c * 8);
    }
}
// single K-major 256 rows x 32
__device__ __forceinline__ void copy256(uint32_t dst, const __half* hi, int ld, int tid) {
#pragma unroll
    for (int i = 0; i < 4; ++i) {
        const int idx = tid + i * 256;
        const int r = idx >> 2, c = idx & 3;
        cp16(dst + (uint32_t)r * 80u + (uint32_t)c * 16u, hi + (size_t)r * ld + c * 8);
    }
}
// single S-major (32 k-rows x 256 cols, pitch 528B)
__device__ __forceinline__ void copyBS1(uint32_t dst, const __half* hi, int ld, int tid) {
#pragma unroll
    for (int i = 0; i < 4; ++i) {
        const int idx = tid + i * 256;
        const int r = idx >> 5, c = idx & 31;
        cp16(dst + (uint32_t)r * 528u + (uint32_t)c * 16u, hi + (size_t)r * ld + c * 8);
    }
}

// ---------------- compute kernels ----------------
// scores: 32x64 warp tile, (Ah + Al) x Bh
__device__ __forceinline__ void compute_sc(uint32_t sb, int wm, int wn, int lane,
                                           float (&acc)[2][8][4]) {
#pragma unroll
    for (int ks = 0; ks < 2; ++ks) {
        const int k0 = ks * 16;
        uint32_t Ah[2][4], Al[2][4], Bh[4][4];
#pragma unroll
        for (int mt = 0; mt < 2; ++mt) {
            const uint32_t ad = sb + (uint32_t)(wm + mt * 16 + (lane & 15)) * 80u +
                                (uint32_t)(k0 + (lane >> 4) * 8) * 2u;
            ldmx4(Ah[mt], ad);
            ldmx4(Al[mt], ad + A_LO);
        }
#pragma unroll
        for (int np = 0; np < 4; ++np) {
            const uint32_t ad = sb + SC_BOFF +
                (uint32_t)(wn + np * 16 + (lane & 7) + (lane >> 4) * 8) * 80u +
                (uint32_t)(k0 + ((lane >> 3) & 1) * 8) * 2u;
            ldmx4(Bh[np], ad);
        }
#pragma unroll
        for (int mt = 0; mt < 2; ++mt)
#pragma unroll
            for (int nt = 0; nt < 8; ++nt) {
                const uint32_t* bh = &Bh[nt >> 1][(nt & 1) * 2];
                mma16816(acc[mt][nt], Ah[mt], bh);
                mma16816(acc[mt][nt], Al[mt], bh);
            }
    }
}
// 64x64 warp tile single product ; BSMAJ selects S-major (trans) B
template <int BSMAJ>
__device__ __forceinline__ void compute1(uint32_t sb, int wm, int wn, int lane,
                                         float (&acc)[4][8][4]) {
#pragma unroll
    for (int ks = 0; ks < 2; ++ks) {
        const int k0 = ks * 16;
        uint32_t Ah[4][4], Bh[4][4];
#pragma unroll
        for (int mt = 0; mt < 4; ++mt) {
            const uint32_t ad = sb + (uint32_t)(wm + mt * 16 + (lane & 15)) * 80u +
                                (uint32_t)(k0 + (lane >> 4) * 8) * 2u;
            ldmx4(Ah[mt], ad);
        }
#pragma unroll
        for (int np = 0; np < 4; ++np) {
            if (BSMAJ) {
                const uint32_t ad = sb + ZO_BOFF +
                    (uint32_t)(k0 + (lane & 7) + ((lane >> 3) & 1) * 8) * 528u +
                    (uint32_t)(wn + np * 16 + (lane >> 4) * 8) * 2u;
                ldmx4t(Bh[np], ad);
            } else {
                const uint32_t ad = sb + ZO_BOFF +
                    (uint32_t)(wn + np * 16 + (lane & 7) + (lane >> 4) * 8) * 80u +
                    (uint32_t)(k0 + ((lane >> 3) & 1) * 8) * 2u;
                ldmx4(Bh[np], ad);
            }
        }
#pragma unroll
        for (int mt = 0; mt < 4; ++mt)
#pragma unroll
            for (int nt = 0; nt < 8; ++nt)
                mma16816(acc[mt][nt], Ah[mt], &Bh[nt >> 1][(nt & 1) * 2]);
    }
}

// z/out prologue: warps 2 (rows) x 4 (cols) -> CTA 128 x 256
#define GEMM_PRE()                                                   \
    extern __shared__ char smraw[];                                  \
    const uint32_t sb = smem_u32(smraw);                             \
    const int tid = threadIdx.x, lane = tid & 31, warp = tid >> 5;   \
    const int wm = (warp & 1) * 64, wn = (warp >> 1) * 64;           \
    float acc[4][8][4];                                              \
    _Pragma("unroll") for (int i = 0; i < 4; ++i)                    \
    _Pragma("unroll") for (int j = 0; j < 8; ++j)                    \
    _Pragma("unroll") for (int q = 0; q < 4; ++q) acc[i][j][q] = 0.f;

// ---------------- aux kernels ----------------
__global__ __launch_bounds__(256) void zero_kernel() {
    g_rowsum[blockIdx.x * 256 + threadIdx.x] = 0.f;
}
__global__ __launch_bounds__(256) void inv_kernel() {
    const int i = blockIdx.x * 256 + threadIdx.x;
    g_invf[i] = 1.0f / g_rowsum[i];
}

__global__ __launch_bounds__(256) void xsplit_kernel(const float* __restrict__ x) {
    const size_t i = (size_t)blockIdx.x * 256 + threadIdx.x;
    float4 v = *(const float4*)(x + i * 4);
    union { __half a[4]; uint2 u; } H, L;
    split_f16(v.x, H.a[0], L.a[0]); split_f16(v.y, H.a[1], L.a[1]);
    split_f16(v.z, H.a[2], L.a[2]); split_f16(v.w, H.a[3], L.a[3]);
    *(uint2*)(g_xh + i * 4) = H.u;
    *(uint2*)(g_xl + i * 4) = L.u;
}

__global__ __launch_bounds__(256) void wsplit_kernel(const float* __restrict__ wt) {
    __shared__ float tile[32][33];
    const int h = blockIdx.z, k0 = blockIdx.y * 32, n0 = blockIdx.x * 32;
    const int tx = threadIdx.x, ty = threadIdx.y;
#pragma unroll
    for (int j = 0; j < 4; ++j)
        tile[ty + 8 * j][tx] = wt[((size_t)h * 1024 + k0 + ty + 8 * j) * 1024 + n0 + tx];
    __syncthreads();
#pragma unroll
    for (int j = 0; j < 4; ++j) {
        const int nn = ty + 8 * j, kk = tx;
        g_wth[((size_t)h * 1024 + n0 + nn) * 1024 + k0 + kk] =
            __float2half_rn(tile[kk][nn]);
    }
}

// ---------------- scores: E = exp(y.yT/8 - 8) + rowsum, 128x128 tile, 2 CTA/SM ----------------
__global__ __launch_bounds__(256, 2) void scores_hmma() {
    extern __shared__ char smraw[];
    const uint32_t sb = smem_u32(smraw);
    const int tid = threadIdx.x, lane = tid & 31, warp = tid >> 5;
    const int wm = (warp & 3) * 32, wn = (warp >> 2) * 64;
    float acc[2][8][4];
#pragma unroll
    for (int i = 0; i < 2; ++i)
#pragma unroll
        for (int j = 0; j < 8; ++j)
#pragma unroll
            for (int q = 0; q < 4; ++q) acc[i][j][q] = 0.f;

    __shared__ float rsum[128];
    const int bh = blockIdx.z, b = bh >> 4, hh = bh & 15;
    const int row0 = blockIdx.y * 128, col0 = blockIdx.x * 128;

    const size_t ab = (size_t)(b * TSEQ + row0) * CEMB + hh * 64;
    const size_t bb = (size_t)(b * TSEQ + col0) * CEMB + hh * 64;

    copyA2(sb, g_xh + ab, g_xl + ab, CEMB, tid);
    copy128(sb + SC_BOFF, g_xh + bb, CEMB, tid);
    cp_commit();
    copyA2(sb + STAGE_SC, g_xh + ab + 32, g_xl + ab + 32, CEMB, tid);
    copy128(sb + STAGE_SC + SC_BOFF, g_xh + bb + 32, CEMB, tid);
    cp_commit();
    if (tid < 128) rsum[tid] = 0.f;
#pragma unroll
    for (int kt = 0; kt < 2; ++kt) {
        if (kt == 0) cp_wait<1>(); else cp_wait<0>();
        __syncthreads();
        compute_sc(sb + kt * STAGE_SC, wm, wn, lane, acc);
        __syncthreads();
    }

    const int g = lane >> 2, t2 = (lane & 3) * 2;
    __half* Ep = g_E + ((size_t)bh * TSEQ + row0) * TSEQ + col0;
    float rs[2][2];
    rs[0][0] = rs[0][1] = rs[1][0] = rs[1][1] = 0.f;
#pragma unroll
    for (int mt = 0; mt < 2; ++mt)
#pragma unroll
        for (int nt = 0; nt < 8; ++nt) {
            const int r = wm + mt * 16 + g, c = wn + nt * 8 + t2;
            const float e0 = __expf(acc[mt][nt][0] * 0.125f - 8.0f);
            const float e1 = __expf(acc[mt][nt][1] * 0.125f - 8.0f);
            const float e2 = __expf(acc[mt][nt][2] * 0.125f - 8.0f);
            const float e3 = __expf(acc[mt][nt][3] * 0.125f - 8.0f);
            rs[mt][0] += e0 + e1;
            rs[mt][1] += e2 + e3;
            *(uint32_t*)(Ep + (size_t)r * TSEQ + c) =
                pack2h(__float2half_rn(e0), __float2half_rn(e1));
            *(uint32_t*)(Ep + (size_t)(r + 8) * TSEQ + c) =
                pack2h(__float2half_rn(e2), __float2half_rn(e3));
        }
#pragma unroll
    for (int mt = 0; mt < 2; ++mt) {
        atomicAdd(&rsum[wm + mt * 16 + g], rs[mt][0]);
        atomicAdd(&rsum[wm + mt * 16 + g + 8], rs[mt][1]);
    }
    __syncthreads();
    if (tid < 128)
        atomicAdd(&g_rowsum[(size_t)bh * TSEQ + row0 + tid], rsum[tid]);
}

// ---------------- Z[h] = X @ W_h (K=1024), paired k-chunks, 3 pair-stages ----------------
__global__ __launch_bounds__(256, 1) void z_hmma() {
    GEMM_PRE();
    const int hh = blockIdx.z;
    const int row0 = blockIdx.y * 128, col0 = blockIdx.x * 256;

    const size_t ab = (size_t)row0 * CEMB;
    const size_t bb = ((size_t)hh * 1024 + col0) * 1024;
    const int NP = 16;

    auto loadP = [&](int t) {
        const uint32_t st = sb + (uint32_t)(t % 3) * PAIR_Z;
        copy128(st, g_xh + ab + (2 * t) * 32, CEMB, tid);
        copy256(st + ZO_BOFF, g_wth + bb + (2 * t) * 32, 1024, tid);
        copy128(st + SUB_Z, g_xh + ab + (2 * t + 1) * 32, CEMB, tid);
        copy256(st + SUB_Z + ZO_BOFF, g_wth + bb + (2 * t + 1) * 32, 1024, tid);
    };
    loadP(0); cp_commit();
    loadP(1); cp_commit();
    for (int pt = 0; pt < NP; ++pt) {
        cp_wait<1>();
        __syncthreads();
        if (pt + 2 < NP) loadP(pt + 2);
        cp_commit();
        const uint32_t st = sb + (uint32_t)(pt % 3) * PAIR_Z;
        compute1<0>(st, wm, wn, lane, acc);
        compute1<0>(st + SUB_Z, wm, wn, lane, acc);
    }

    const int g = lane >> 2, t2 = (lane & 3) * 2;
#pragma unroll
    for (int mt = 0; mt < 4; ++mt)
#pragma unroll
        for (int nt = 0; nt < 8; ++nt) {
            const int r = row0 + wm + mt * 16 + g;
            const int c = col0 + wn + nt * 8 + t2;
            const size_t o0 = ((size_t)hh * 4096 + r) * 1024 + c;
            *(uint32_t*)(g_Zh + o0) =
                pack2h(__float2half_rn(acc[mt][nt][0]), __float2half_rn(acc[mt][nt][1]));
            *(uint32_t*)(g_Zh + o0 + 8 * 1024) =
                pack2h(__float2half_rn(acc[mt][nt][2]), __float2half_rn(acc[mt][nt][3]));
        }
}

// ---------------- out[b] = sum_h inv_h * (E_h @ Z[h,b]), head-boundary rescale ----------------
__global__ __launch_bounds__(256, 1) void out_hmma(float* __restrict__ out) {
    GEMM_PRE();
    const int b = blockIdx.z;
    const int row0 = blockIdx.y * 128, col0 = blockIdx.x * 256;
    const int g = lane >> 2;

    const size_t arow = ((size_t)(b * 16) * TSEQ + row0) * TSEQ;
    const int NQ = 256;                          // 256 quads of k32 ; head = qt>>4
    auto loadQ = [&](int t) {
        const uint32_t st = sb + (uint32_t)(t & 1) * QUAD_O;
#pragma unroll
        for (int j = 0; j < 4; ++j) {
            const int u = 4 * t + j;
            const int hh = u >> 6, s0 = (u & 63) * 32;
            const size_t ap = arow + (size_t)hh * TSEQ * TSEQ + s0;
            const size_t bp = ((size_t)hh * 4096 + b * TSEQ + s0) * 1024 + col0;
            const uint32_t ss = st + (uint32_t)j * SUB_O;
            copy128(ss, g_E + ap, TSEQ, tid);
            copyBS1(ss + ZO_BOFF, g_Zh + bp, 1024, tid);
        }
    };
    loadQ(0); cp_commit();

    float inv_cur[4][2];
    int curh = -1;
    for (int qt = 0; qt < NQ; ++qt) {
        const int hh = qt >> 4;
        if (hh != curh) {
            const float* invp = g_invf + ((size_t)(b * 16 + hh)) * TSEQ + row0;
            const float* rsp = g_rowsum + ((size_t)(b * 16 + hh)) * TSEQ + row0;
            if (curh >= 0) {
                // acc *= inv_old / inv_new = inv_old * rowsum_new  (per row)
#pragma unroll
                for (int mt = 0; mt < 4; ++mt) {
                    const int r = wm + mt * 16 + g;
                    const float r0 = inv_cur[mt][0] * rsp[r];
                    const float r1 = inv_cur[mt][1] * rsp[r + 8];
#pragma unroll
                    for (int nt = 0; nt < 8; ++nt) {
                        acc[mt][nt][0] *= r0; acc[mt][nt][1] *= r0;
                        acc[mt][nt][2] *= r1; acc[mt][nt][3] *= r1;
                    }
                }
            }
#pragma unroll
            for (int mt = 0; mt < 4; ++mt) {
                const int r = wm + mt * 16 + g;
                inv_cur[mt][0] = invp[r];
                inv_cur[mt][1] = invp[r + 8];
            }
            curh = hh;
        }
        cp_wait<0>();
        __syncthreads();
        if (qt + 1 < NQ) loadQ(qt + 1);
        cp_commit();
        const uint32_t st = sb + (uint32_t)(qt & 1) * QUAD_O;
        compute1<1>(st, wm, wn, lane, acc);
        compute1<1>(st + SUB_O, wm, wn, lane, acc);
        compute1<1>(st + 2 * SUB_O, wm, wn, lane, acc);
        compute1<1>(st + 3 * SUB_O, wm, wn, lane, acc);
    }

    const int t2 = (lane & 3) * 2;
    float* Op = out + ((size_t)(b * TSEQ + row0)) * CEMB + col0;
#pragma unroll
    for (int mt = 0; mt < 4; ++mt)
#pragma unroll
        for (int nt = 0; nt < 8; ++nt) {
            const int r = wm + mt * 16 + g, c = wn + nt * 8 + t2;
            *(float2*)(Op + (size_t)r * CEMB + c) =
                make_float2(acc[mt][nt][0] * inv_cur[mt][0], acc[mt][nt][1] * inv_cur[mt][0]);
            *(float2*)(Op + (size_t)(r + 8) * CEMB + c) =
                make_float2(acc[mt][nt][2] * inv_cur[mt][1], acc[mt][nt][3] * inv_cur[mt][1]);
        }
}

// ---------------------------------------------------------------------------
extern "C" void kernel_launch(void* const* d_in, const int* in_sizes, int n_in,
                              void* d_out, int out_size) {
    const float* x  = (const float*)d_in[0];   // [2,2048,1024]
    const float* wt = (const float*)d_in[1];   // [16384,1024]
    float* out = (float*)d_out;

    cudaFuncSetAttribute(scores_hmma, cudaFuncAttributeMaxDynamicSharedMemorySize, SMEM_SC);
    cudaFuncSetAttribute(z_hmma,      cudaFuncAttributeMaxDynamicSharedMemorySize, SMEM_Z);
    cudaFuncSetAttribute(out_hmma,    cudaFuncAttributeMaxDynamicSharedMemorySize, SMEM_O);

    zero_kernel<<<256, 256>>>();
    xsplit_kernel<<<4096, 256>>>(x);
    wsplit_kernel<<<dim3(32, 32, 16), dim3(32, 8)>>>(wt);
    scores_hmma<<<dim3(16, 16, 32), 256, SMEM_SC>>>();
    inv_kernel<<<256, 256>>>();
    z_hmma<<<dim3(4, 32, 16), 256, SMEM_Z>>>();
    out_hmma<<<dim3(4, 16, 2), 256, SMEM_O>>>(out);
}

// round 15
// speedup vs baseline: 1.0667x; 1.0270x over previous
#include <cuda_runtime.h>
#include <cuda_fp16.h>
#include <cstdint>

#define TSEQ 2048
#define CEMB 1024

// ---------------- scratch ----------------
__device__ __align__(128) __half g_E[134217728];     // [2,16,2048,2048] exp(S-8) fp16
__device__ __align__(128) float  g_rowsum[65536];    // [2,16,2048] fp32 sums
__device__ __align__(128) float  g_invf[65536];      // 1/rowsum fp32
__device__ __align__(128) __half g_xh[4194304];      // [4096,1024] x hi
__device__ __align__(128) __half g_xl[4194304];      // x lo (scores A only)
__device__ __align__(128) __half g_wth[16777216];    // Wt[h][n][k] fp16
__device__ __align__(128) __half g_Zh[67108864];     // [16][4096 r][1024 c] fp16

// ---------------- low-level helpers ----------------
__device__ __forceinline__ uint32_t smem_u32(const void* p) {
    uint32_t a;
    asm("{ .reg .u64 t; cvta.to.shared.u64 t, %1; cvt.u32.u64 %0, t; }" : "=r"(a) : "l"(p));
    return a;
}
__device__ __forceinline__ void cp16(uint32_t dst, const void* src) {
    asm volatile("cp.async.cg.shared.global [%0], [%1], 16;" :: "r"(dst), "l"(src));
}
__device__ __forceinline__ void cp_commit() { asm volatile("cp.async.commit_group;" ::: "memory"); }
template <int N> __device__ __forceinline__ void cp_wait() {
    asm volatile("cp.async.wait_group %0;" :: "n"(N) : "memory");
}
__device__ __forceinline__ void ldmx4(uint32_t r[4], uint32_t a) {
    asm volatile("ldmatrix.sync.aligned.m8n8.x4.shared.b16 {%0,%1,%2,%3}, [%4];"
                 : "=r"(r[0]), "=r"(r[1]), "=r"(r[2]), "=r"(r[3]) : "r"(a));
}
__device__ __forceinline__ void ldmx4t(uint32_t r[4], uint32_t a) {
    asm volatile("ldmatrix.sync.aligned.m8n8.x4.trans.shared.b16 {%0,%1,%2,%3}, [%4];"
                 : "=r"(r[0]), "=r"(r[1]), "=r"(r[2]), "=r"(r[3]) : "r"(a));
}
__device__ __forceinline__ void mma16816(float* c, const uint32_t* a, const uint32_t* b) {
    asm volatile(
        "mma.sync.aligned.m16n8k16.row.col.f32.f16.f16.f32 "
        "{%0,%1,%2,%3}, {%4,%5,%6,%7}, {%8,%9}, {%0,%1,%2,%3};"
        : "+f"(c[0]), "+f"(c[1]), "+f"(c[2]), "+f"(c[3])
        : "r"(a[0]), "r"(a[1]), "r"(a[2]), "r"(a[3]), "r"(b[0]), "r"(b[1]));
}
__device__ __forceinline__ void split_f16(float v, __half& hi, __half& lo) {
    hi = __float2half_rn(v);
    lo = __float2half_rn(v - __half2float(hi));
}
__device__ __forceinline__ uint32_t pack2h(__half a, __half b) {
    union { __half h[2]; uint32_t u; } v; v.h[0] = a; v.h[1] = b; return v.u;
}

// ---------------- smem layouts ----------------
// scores (persistent): A full (2 k32 subs, hi+lo) 40960 ; B: 3 bufs x (2 k32 subs) 20480
// z (128x256): sub = A@0 + BK@10240 : SUB_Z = 30720 ; 3 pairs
// out (128x256): sub = A@0 + BS@10240 : SUB_O = 27136 ; 2 quads
#define SUBK     10240u
#define A_FULL   40960u
#define B_BUF    20480u
#define ZO_BOFF  10240u
#define SUB_Z    30720u
#define PAIR_Z   61440u
#define SUB_O    27136u
#define QUAD_O   108544u
#define SMEM_SC  (A_FULL + 3 * B_BUF)
#define SMEM_Z   (3 * PAIR_Z)
#define SMEM_O   (2 * QUAD_O)

// single K-major 128 rows x 32 (one k32 subtile, pitch 80B)
__device__ __forceinline__ void copy128(uint32_t dst, const __half* src, int ld, int tid) {
#pragma unroll
    for (int i = 0; i < 2; ++i) {
        const int idx = tid + i * 256;
        const int r = idx >> 2, c = idx & 3;
        cp16(dst + (uint32_t)r * 80u + (uint32_t)c * 16u, src + (size_t)r * ld + c * 8);
    }
}
// single K-major 256 rows x 32
__device__ __forceinline__ void copy256(uint32_t dst, const __half* src, int ld, int tid) {
#pragma unroll
    for (int i = 0; i < 4; ++i) {
        const int idx = tid + i * 256;
        const int r = idx >> 2, c = idx & 3;
        cp16(dst + (uint32_t)r * 80u + (uint32_t)c * 16u, src + (size_t)r * ld + c * 8);
    }
}
// single S-major (32 k-rows x 256 cols, pitch 528B)
__device__ __forceinline__ void copyBS1(uint32_t dst, const __half* src, int ld, int tid) {
#pragma unroll
    for (int i = 0; i < 4; ++i) {
        const int idx = tid + i * 256;
        const int r = idx >> 5, c = idx & 31;
        cp16(dst + (uint32_t)r * 528u + (uint32_t)c * 16u, src + (size_t)r * ld + c * 8);
    }
}

// ---------------- compute kernels ----------------
// scores: 32x64 warp tile, (Ah + Al) x Bh over one k32 subtile
__device__ __forceinline__ void compute_sc32(uint32_t aHi, uint32_t bB, int wm, int wn,
                                             int lane, float (&acc)[2][8][4]) {
#pragma unroll
    for (int ks = 0; ks < 2; ++ks) {
        const int k0 = ks * 16;
        uint32_t Ah[2][4], Al[2][4], Bh[4][4];
#pragma unroll
        for (int mt = 0; mt < 2; ++mt) {
            const uint32_t ad = aHi + (uint32_t)(wm + mt * 16 + (lane & 15)) * 80u +
                                (uint32_t)(k0 + (lane >> 4) * 8) * 2u;
            ldmx4(Ah[mt], ad);
            ldmx4(Al[mt], ad + A_FULL / 2);    // lo plane at +20480
        }
#pragma unroll
        for (int np = 0; np < 4; ++np) {
            const uint32_t ad = bB +
                (uint32_t)(wn + np * 16 + (lane & 7) + (lane >> 4) * 8) * 80u +
                (uint32_t)(k0 + ((lane >> 3) & 1) * 8) * 2u;
            ldmx4(Bh[np], ad);
        }
#pragma unroll
        for (int mt = 0; mt < 2; ++mt)
#pragma unroll
            for (int nt = 0; nt < 8; ++nt) {
                const uint32_t* bh = &Bh[nt >> 1][(nt & 1) * 2];
                mma16816(acc[mt][nt], Ah[mt], bh);
                mma16816(acc[mt][nt], Al[mt], bh);
            }
    }
}
// 64x64 warp tile single product ; BSMAJ selects S-major (trans) B
template <int BSMAJ>
__device__ __forceinline__ void compute1(uint32_t sb, int wm, int wn, int lane,
                                         float (&acc)[4][8][4]) {
#pragma unroll
    for (int ks = 0; ks < 2; ++ks) {
        const int k0 = ks * 16;
        uint32_t Ah[4][4], Bh[4][4];
#pragma unroll
        for (int mt = 0; mt < 4; ++mt) {
            const uint32_t ad = sb + (uint32_t)(wm + mt * 16 + (lane & 15)) * 80u +
                                (uint32_t)(k0 + (lane >> 4) * 8) * 2u;
            ldmx4(Ah[mt], ad);
        }
#pragma unroll
        for (int np = 0; np < 4; ++np) {
            if (BSMAJ) {
                const uint32_t ad = sb + ZO_BOFF +
                    (uint32_t)(k0 + (lane & 7) + ((lane >> 3) & 1) * 8) * 528u +
                    (uint32_t)(wn + np * 16 + (lane >> 4) * 8) * 2u;
                ldmx4t(Bh[np], ad);
            } else {
                const uint32_t ad = sb + ZO_BOFF +
                    (uint32_t)(wn + np * 16 + (lane & 7) + (lane >> 4) * 8) * 80u +
                    (uint32_t)(k0 + ((lane >> 3) & 1) * 8) * 2u;
                ldmx4(Bh[np], ad);
            }
        }
#pragma unroll
        for (int mt = 0; mt < 4; ++mt)
#pragma unroll
            for (int nt = 0; nt < 8; ++nt)
                mma16816(acc[mt][nt], Ah[mt], &Bh[nt >> 1][(nt & 1) * 2]);
    }
}

#define GEMM_PRE()                                                   \
    extern __shared__ char smraw[];                                  \
    const uint32_t sb = smem_u32(smraw);                             \
    const int tid = threadIdx.x, lane = tid & 31, warp = tid >> 5;   \
    const int wm = (warp & 1) * 64, wn = (warp >> 1) * 64;           \
    float acc[4][8][4];                                              \
    _Pragma("unroll") for (int i = 0; i < 4; ++i)                    \
    _Pragma("unroll") for (int j = 0; j < 8; ++j)                    \
    _Pragma("unroll") for (int q = 0; q < 4; ++q) acc[i][j][q] = 0.f;

// ---------------- aux kernels ----------------
__global__ __launch_bounds__(256) void xsplit_kernel(const float* __restrict__ x) {
    const size_t i = (size_t)blockIdx.x * 256 + threadIdx.x;
    float4 v = *(const float4*)(x + i * 4);
    union { __half a[4]; uint2 u; } H, L;
    split_f16(v.x, H.a[0], L.a[0]); split_f16(v.y, H.a[1], L.a[1]);
    split_f16(v.z, H.a[2], L.a[2]); split_f16(v.w, H.a[3], L.a[3]);
    *(uint2*)(g_xh + i * 4) = H.u;
    *(uint2*)(g_xl + i * 4) = L.u;
}

__global__ __launch_bounds__(256) void wsplit_kernel(const float* __restrict__ wt) {
    __shared__ float tile[32][33];
    const int h = blockIdx.z, k0 = blockIdx.y * 32, n0 = blockIdx.x * 32;
    const int tx = threadIdx.x, ty = threadIdx.y;
#pragma unroll
    for (int j = 0; j < 4; ++j)
        tile[ty + 8 * j][tx] = wt[((size_t)h * 1024 + k0 + ty + 8 * j) * 1024 + n0 + tx];
    __syncthreads();
#pragma unroll
    for (int j = 0; j < 4; ++j) {
        const int nn = ty + 8 * j, kk = tx;
        g_wth[((size_t)h * 1024 + n0 + nn) * 1024 + k0 + kk] =
            __float2half_rn(tile[kk][nn]);
    }
}

// ---------------- scores: persistent row-tile, loops all 16 col tiles ----------------
// A full (hi@0..20480, lo@20480..40960, two k32 subs each 10240)
// B bufs at A_FULL + buf*B_BUF (two k32 subs)
__global__ __launch_bounds__(256, 2) void scores_hmma() {
    extern __shared__ char smraw[];
    const uint32_t sb = smem_u32(smraw);
    const int tid = threadIdx.x, lane = tid & 31, warp = tid >> 5;
    const int wm = (warp & 3) * 32, wn = (warp >> 2) * 64;
    __shared__ float rsum[128];

    const int bh = blockIdx.y, b = bh >> 4, hh = bh & 15;
    const int row0 = blockIdx.x * 128;

    const size_t ab = (size_t)(b * TSEQ + row0) * CEMB + hh * 64;
    const size_t bbase = (size_t)(b * TSEQ) * CEMB + hh * 64;

    // A: hi k0 @0, hi k1 @10240, lo k0 @20480, lo k1 @30720
    copy128(sb, g_xh + ab, CEMB, tid);
    copy128(sb + SUBK, g_xh + ab + 32, CEMB, tid);
    copy128(sb + 2 * SUBK, g_xl + ab, CEMB, tid);
    copy128(sb + 3 * SUBK, g_xl + ab + 32, CEMB, tid);
    auto loadB = [&](int ct) {
        const uint32_t dst = sb + A_FULL + (uint32_t)(ct % 3) * B_BUF;
        const __half* src = g_xh + bbase + (size_t)(ct * 128) * CEMB;
        copy128(dst, src, CEMB, tid);
        copy128(dst + SUBK, src + 32, CEMB, tid);
    };
    loadB(0); cp_commit();        // group: A + B0
    loadB(1); cp_commit();        // group: B1
    if (tid < 128) rsum[tid] = 0.f;

    const int g = lane >> 2, t2 = (lane & 3) * 2;
    float rs[2][2];
    rs[0][0] = rs[0][1] = rs[1][0] = rs[1][1] = 0.f;

    for (int ct = 0; ct < 16; ++ct) {
        cp_wait<1>();
        __syncthreads();
        if (ct + 2 < 16) loadB(ct + 2);
        cp_commit();

        float acc[2][8][4];
#pragma unroll
        for (int i = 0; i < 2; ++i)
#pragma unroll
            for (int j = 0; j < 8; ++j)
#pragma unroll
                for (int q = 0; q < 4; ++q) acc[i][j][q] = 0.f;

        const uint32_t bB = sb + A_FULL + (uint32_t)(ct % 3) * B_BUF;
        compute_sc32(sb, bB, wm, wn, lane, acc);
        compute_sc32(sb + SUBK, bB + SUBK, wm, wn, lane, acc);

        __half* Ep = g_E + ((size_t)bh * TSEQ + row0) * TSEQ + ct * 128;
#pragma unroll
        for (int mt = 0; mt < 2; ++mt)
#pragma unroll
            for (int nt = 0; nt < 8; ++nt) {
                const int r = wm + mt * 16 + g, c = wn + nt * 8 + t2;
                const float e0 = __expf(acc[mt][nt][0] * 0.125f - 8.0f);
                const float e1 = __expf(acc[mt][nt][1] * 0.125f - 8.0f);
                const float e2 = __expf(acc[mt][nt][2] * 0.125f - 8.0f);
                const float e3 = __expf(acc[mt][nt][3] * 0.125f - 8.0f);
                rs[mt][0] += e0 + e1;
                rs[mt][1] += e2 + e3;
                *(uint32_t*)(Ep + (size_t)r * TSEQ + c) =
                    pack2h(__float2half_rn(e0), __float2half_rn(e1));
                *(uint32_t*)(Ep + (size_t)(r + 8) * TSEQ + c) =
                    pack2h(__float2half_rn(e2), __float2half_rn(e3));
            }
    }

#pragma unroll
    for (int mt = 0; mt < 2; ++mt) {
        atomicAdd(&rsum[wm + mt * 16 + g], rs[mt][0]);
        atomicAdd(&rsum[wm + mt * 16 + g + 8], rs[mt][1]);
    }
    __syncthreads();
    if (tid < 128) {
        const float s = rsum[tid];
        const size_t idx = (size_t)bh * TSEQ + row0 + tid;
        g_rowsum[idx] = s;
        g_invf[idx] = 1.0f / s;
    }
}

// ---------------- Z[h] = X @ W_h (K=1024), paired k-chunks, 3 pair-stages ----------------
__global__ __launch_bounds__(256, 1) void z_hmma() {
    GEMM_PRE();
    const int hh = blockIdx.z;
    const int row0 = blockIdx.y * 128, col0 = blockIdx.x * 256;

    const size_t ab = (size_t)row0 * CEMB;
    const size_t bb = ((size_t)hh * 1024 + col0) * 1024;
    const int NP = 16;

    auto loadP = [&](int t) {
        const uint32_t st = sb + (uint32_t)(t % 3) * PAIR_Z;
        copy128(st, g_xh + ab + (2 * t) * 32, CEMB, tid);
        copy256(st + ZO_BOFF, g_wth + bb + (2 * t) * 32, 1024, tid);
        copy128(st + SUB_Z, g_xh + ab + (2 * t + 1) * 32, CEMB, tid);
        copy256(st + SUB_Z + ZO_BOFF, g_wth + bb + (2 * t + 1) * 32, 1024, tid);
    };
    loadP(0); cp_commit();
    loadP(1); cp_commit();
    for (int pt = 0; pt < NP; ++pt) {
        cp_wait<1>();
        __syncthreads();
        if (pt + 2 < NP) loadP(pt + 2);
        cp_commit();
        const uint32_t st = sb + (uint32_t)(pt % 3) * PAIR_Z;
        compute1<0>(st, wm, wn, lane, acc);
        compute1<0>(st + SUB_Z, wm, wn, lane, acc);
    }

    const int g = lane >> 2, t2 = (lane & 3) * 2;
#pragma unroll
    for (int mt = 0; mt < 4; ++mt)
#pragma unroll
        for (int nt = 0; nt < 8; ++nt) {
            const int r = row0 + wm + mt * 16 + g;
            const int c = col0 + wn + nt * 8 + t2;
            const size_t o0 = ((size_t)hh * 4096 + r) * 1024 + c;
            *(uint32_t*)(g_Zh + o0) =
                pack2h(__float2half_rn(acc[mt][nt][0]), __float2half_rn(acc[mt][nt][1]));
            *(uint32_t*)(g_Zh + o0 + 8 * 1024) =
                pack2h(__float2half_rn(acc[mt][nt][2]), __float2half_rn(acc[mt][nt][3]));
        }
}

// ---------------- out[b] = sum_h inv_h * (E_h @ Z[h,b]), head-boundary rescale ----------------
__global__ __launch_bounds__(256, 1) void out_hmma(float* __restrict__ out) {
    GEMM_PRE();
    const int b = blockIdx.z;
    const int row0 = blockIdx.y * 128, col0 = blockIdx.x * 256;
    const int g = lane >> 2;

    const size_t arow = ((size_t)(b * 16) * TSEQ + row0) * TSEQ;
    const int NQ = 256;                          // 256 quads of k32 ; head = qt>>4
    auto loadQ = [&](int t) {
        const uint32_t st = sb + (uint32_t)(t & 1) * QUAD_O;
#pragma unroll
        for (int j = 0; j < 4; ++j) {
            const int u = 4 * t + j;
            const int hh = u >> 6, s0 = (u & 63) * 32;
            const size_t ap = arow + (size_t)hh * TSEQ * TSEQ + s0;
            const size_t bp = ((size_t)hh * 4096 + b * TSEQ + s0) * 1024 + col0;
            const uint32_t ss = st + (uint32_t)j * SUB_O;
            copy128(ss, g_E + ap, TSEQ, tid);
            copyBS1(ss + ZO_BOFF, g_Zh + bp, 1024, tid);
        }
    };
    loadQ(0); cp_commit();

    float inv_cur[4][2];
    int curh = -1;
    for (int qt = 0; qt < NQ; ++qt) {
        const int hh = qt >> 4;
        if (hh != curh) {
            const float* invp = g_invf + ((size_t)(b * 16 + hh)) * TSEQ + row0;
            const float* rsp = g_rowsum + ((size_t)(b * 16 + hh)) * TSEQ + row0;
            if (curh >= 0) {
#pragma unroll
                for (int mt = 0; mt < 4; ++mt) {
                    const int r = wm + mt * 16 + g;
                    const float r0 = inv_cur[mt][0] * rsp[r];
                    const float r1 = inv_cur[mt][1] * rsp[r + 8];
#pragma unroll
                    for (int nt = 0; nt < 8; ++nt) {
                        acc[mt][nt][0] *= r0; acc[mt][nt][1] *= r0;
                        acc[mt][nt][2] *= r1; acc[mt][nt][3] *= r1;
                    }
                }
            }
#pragma unroll
            for (int mt = 0; mt < 4; ++mt) {
                const int r = wm + mt * 16 + g;
                inv_cur[mt][0] = invp[r];
                inv_cur[mt][1] = invp[r + 8];
            }
            curh = hh;
        }
        cp_wait<0>();
        __syncthreads();
        if (qt + 1 < NQ) loadQ(qt + 1);
        cp_commit();
        const uint32_t st = sb + (uint32_t)(qt & 1) * QUAD_O;
        compute1<1>(st, wm, wn, lane, acc);
        compute1<1>(st + SUB_O, wm, wn, lane, acc);
        compute1<1>(st + 2 * SUB_O, wm, wn, lane, acc);
        compute1<1>(st + 3 * SUB_O, wm, wn, lane, acc);
    }

    const int t2 = (lane & 3) * 2;
    float* Op = out + ((size_t)(b * TSEQ + row0)) * CEMB + col0;
#pragma unroll
    for (int mt = 0; mt < 4; ++mt)
#pragma unroll
        for (int nt = 0; nt < 8; ++nt) {
            const int r = wm + mt * 16 + g, c = wn + nt * 8 + t2;
            *(float2*)(Op + (size_t)r * CEMB + c) =
                make_float2(acc[mt][nt][0] * inv_cur[mt][0], acc[mt][nt][1] * inv_cur[mt][0]);
            *(float2*)(Op + (size_t)(r + 8) * CEMB + c) =
                make_float2(acc[mt][nt][2] * inv_cur[mt][1], acc[mt][nt][3] * inv_cur[mt][1]);
        }
}

// ---------------------------------------------------------------------------
extern "C" void kernel_launch(void* const* d_in, const int* in_sizes, int n_in,
                              void* d_out, int out_size) {
    const float* x  = (const float*)d_in[0];   // [2,2048,1024]
    const float* wt = (const float*)d_in[1];   // [16384,1024]
    float* out = (float*)d_out;

    cudaFuncSetAttribute(scores_hmma, cudaFuncAttributeMaxDynamicSharedMemorySize, SMEM_SC);
    cudaFuncSetAttribute(z_hmma,      cudaFuncAttributeMaxDynamicSharedMemorySize, SMEM_Z);
    cudaFuncSetAttribute(out_hmma,    cudaFuncAttributeMaxDynamicSharedMemorySize, SMEM_O);

    xsplit_kernel<<<4096, 256>>>(x);
    wsplit_kernel<<<dim3(32, 32, 16), dim3(32, 8)>>>(wt);
    scores_hmma<<<dim3(16, 32), 256, SMEM_SC>>>();
    z_hmma<<<dim3(4, 32, 16), 256, SMEM_Z>>>();
    out_hmma<<<dim3(4, 16, 2), 256, SMEM_O>>>(out);
}

// round 16
// speedup vs baseline: 1.1126x; 1.0431x over previous
#include <cuda_runtime.h>
#include <cuda_fp16.h>
#include <cstdint>

#define TSEQ 2048
#define CEMB 1024

// ---------------- scratch ----------------
__device__ __align__(128) __half g_E[134217728];     // [2,16,2048,2048] exp(S-8) fp16
__device__ __align__(128) float  g_rowsum[65536];    // [2,16,2048] fp32 sums
__device__ __align__(128) float  g_invf[65536];      // 1/rowsum fp32
__device__ __align__(128) __half g_xh[4194304];      // [4096,1024] x hi
__device__ __align__(128) __half g_xl[4194304];      // x lo (scores A only)
__device__ __align__(128) __half g_wth[16777216];    // Wt[h][n][k] fp16
__device__ __align__(128) __half g_Zh[67108864];     // [16][4096 r][1024 c] fp16

// ---------------- low-level helpers ----------------
__device__ __forceinline__ uint32_t smem_u32(const void* p) {
    uint32_t a;
    asm("{ .reg .u64 t; cvta.to.shared.u64 t, %1; cvt.u32.u64 %0, t; }" : "=r"(a) : "l"(p));
    return a;
}
__device__ __forceinline__ void cp16(uint32_t dst, const void* src) {
    asm volatile("cp.async.cg.shared.global [%0], [%1], 16;" :: "r"(dst), "l"(src));
}
__device__ __forceinline__ void cp_commit() { asm volatile("cp.async.commit_group;" ::: "memory"); }
template <int N> __device__ __forceinline__ void cp_wait() {
    asm volatile("cp.async.wait_group %0;" :: "n"(N) : "memory");
}
__device__ __forceinline__ void ldmx4(uint32_t r[4], uint32_t a) {
    asm volatile("ldmatrix.sync.aligned.m8n8.x4.shared.b16 {%0,%1,%2,%3}, [%4];"
                 : "=r"(r[0]), "=r"(r[1]), "=r"(r[2]), "=r"(r[3]) : "r"(a));
}
__device__ __forceinline__ void ldmx4t(uint32_t r[4], uint32_t a) {
    asm volatile("ldmatrix.sync.aligned.m8n8.x4.trans.shared.b16 {%0,%1,%2,%3}, [%4];"
                 : "=r"(r[0]), "=r"(r[1]), "=r"(r[2]), "=r"(r[3]) : "r"(a));
}
__device__ __forceinline__ void mma16816(float* c, const uint32_t* a, const uint32_t* b) {
    asm volatile(
        "mma.sync.aligned.m16n8k16.row.col.f32.f16.f16.f32 "
        "{%0,%1,%2,%3}, {%4,%5,%6,%7}, {%8,%9}, {%0,%1,%2,%3};"
        : "+f"(c[0]), "+f"(c[1]), "+f"(c[2]), "+f"(c[3])
        : "r"(a[0]), "r"(a[1]), "r"(a[2]), "r"(a[3]), "r"(b[0]), "r"(b[1]));
}
__device__ __forceinline__ void split_f16(float v, __half& hi, __half& lo) {
    hi = __float2half_rn(v);
    lo = __float2half_rn(v - __half2float(hi));
}
__device__ __forceinline__ uint32_t pack2h(__half a, __half b) {
    union { __half h[2]; uint32_t u; } v; v.h[0] = a; v.h[1] = b; return v.u;
}

// ---------------- smem layouts ----------------
// scores (persistent): A full 40960 ; B: 3 bufs x 20480
// z (128x128, 2 CTA/SM): sub(k32) = A@0 + B@10240 = 20480 ; pair = 40960 ; 2 pairs
// out (128x256): sub = A@0 + BS@10240 : SUB_O = 27136 ; 2 quads
#define SUBK     10240u
#define A_FULL   40960u
#define B_BUF    20480u
#define ZO_BOFF  10240u
#define PAIR_Z   40960u
#define SUB_O    27136u
#define QUAD_O   108544u
#define SMEM_SC  (A_FULL + 3 * B_BUF)
#define SMEM_Z   (2 * PAIR_Z)
#define SMEM_O   (2 * QUAD_O)

// single K-major 128 rows x 32 (one k32 subtile, pitch 80B)
__device__ __forceinline__ void copy128(uint32_t dst, const __half* src, int ld, int tid) {
#pragma unroll
    for (int i = 0; i < 2; ++i) {
        const int idx = tid + i * 256;
        const int r = idx >> 2, c = idx & 3;
        cp16(dst + (uint32_t)r * 80u + (uint32_t)c * 16u, src + (size_t)r * ld + c * 8);
    }
}
// single S-major (32 k-rows x 256 cols, pitch 528B)
__device__ __forceinline__ void copyBS1(uint32_t dst, const __half* src, int ld, int tid) {
#pragma unroll
    for (int i = 0; i < 4; ++i) {
        const int idx = tid + i * 256;
        const int r = idx >> 5, c = idx & 31;
        cp16(dst + (uint32_t)r * 528u + (uint32_t)c * 16u, src + (size_t)r * ld + c * 8);
    }
}

// ---------------- compute kernels ----------------
// scores: 32x64 warp tile, (Ah + Al) x Bh over one k32 subtile
__device__ __forceinline__ void compute_sc32(uint32_t aHi, uint32_t bB, int wm, int wn,
                                             int lane, float (&acc)[2][8][4]) {
#pragma unroll
    for (int ks = 0; ks < 2; ++ks) {
        const int k0 = ks * 16;
        uint32_t Ah[2][4], Al[2][4], Bh[4][4];
#pragma unroll
        for (int mt = 0; mt < 2; ++mt) {
            const uint32_t ad = aHi + (uint32_t)(wm + mt * 16 + (lane & 15)) * 80u +
                                (uint32_t)(k0 + (lane >> 4) * 8) * 2u;
            ldmx4(Ah[mt], ad);
            ldmx4(Al[mt], ad + A_FULL / 2);    // lo plane at +20480
        }
#pragma unroll
        for (int np = 0; np < 4; ++np) {
            const uint32_t ad = bB +
                (uint32_t)(wn + np * 16 + (lane & 7) + (lane >> 4) * 8) * 80u +
                (uint32_t)(k0 + ((lane >> 3) & 1) * 8) * 2u;
            ldmx4(Bh[np], ad);
        }
#pragma unroll
        for (int mt = 0; mt < 2; ++mt)
#pragma unroll
            for (int nt = 0; nt < 8; ++nt) {
                const uint32_t* bh = &Bh[nt >> 1][(nt & 1) * 2];
                mma16816(acc[mt][nt], Ah[mt], bh);
                mma16816(acc[mt][nt], Al[mt], bh);
            }
    }
}
// z: 32x64 warp tile single product, K-major B (A@st, B@st+10240), one k32 sub
__device__ __forceinline__ void compute_z32(uint32_t st, int wm, int wn, int lane,
                                            float (&acc)[2][8][4]) {
#pragma unroll
    for (int ks = 0; ks < 2; ++ks) {
        const int k0 = ks * 16;
        uint32_t Ah[2][4], Bh[4][4];
#pragma unroll
        for (int mt = 0; mt < 2; ++mt) {
            const uint32_t ad = st + (uint32_t)(wm + mt * 16 + (lane & 15)) * 80u +
                                (uint32_t)(k0 + (lane >> 4) * 8) * 2u;
            ldmx4(Ah[mt], ad);
        }
#pragma unroll
        for (int np = 0; np < 4; ++np) {
            const uint32_t ad = st + SUBK +
                (uint32_t)(wn + np * 16 + (lane & 7) + (lane >> 4) * 8) * 80u +
                (uint32_t)(k0 + ((lane >> 3) & 1) * 8) * 2u;
            ldmx4(Bh[np], ad);
        }
#pragma unroll
        for (int mt = 0; mt < 2; ++mt)
#pragma unroll
            for (int nt = 0; nt < 8; ++nt)
                mma16816(acc[mt][nt], Ah[mt], &Bh[nt >> 1][(nt & 1) * 2]);
    }
}
// out: 64x64 warp tile single product, S-major (trans) B
__device__ __forceinline__ void compute_o(uint32_t sb, int wm, int wn, int lane,
                                          float (&acc)[4][8][4]) {
#pragma unroll
    for (int ks = 0; ks < 2; ++ks) {
        const int k0 = ks * 16;
        uint32_t Ah[4][4], Bh[4][4];
#pragma unroll
        for (int mt = 0; mt < 4; ++mt) {
            const uint32_t ad = sb + (uint32_t)(wm + mt * 16 + (lane & 15)) * 80u +
                                (uint32_t)(k0 + (lane >> 4) * 8) * 2u;
            ldmx4(Ah[mt], ad);
        }
#pragma unroll
        for (int np = 0; np < 4; ++np) {
            const uint32_t ad = sb + ZO_BOFF +
                (uint32_t)(k0 + (lane & 7) + ((lane >> 3) & 1) * 8) * 528u +
                (uint32_t)(wn + np * 16 + (lane >> 4) * 8) * 2u;
            ldmx4t(Bh[np], ad);
        }
#pragma unroll
        for (int mt = 0; mt < 4; ++mt)
#pragma unroll
            for (int nt = 0; nt < 8; ++nt)
                mma16816(acc[mt][nt], Ah[mt], &Bh[nt >> 1][(nt & 1) * 2]);
    }
}

// ---------------- aux kernels ----------------
__global__ __launch_bounds__(256) void xsplit_kernel(const float* __restrict__ x) {
    const size_t i = (size_t)blockIdx.x * 256 + threadIdx.x;
    float4 v = *(const float4*)(x + i * 4);
    union { __half a[4]; uint2 u; } H, L;
    split_f16(v.x, H.a[0], L.a[0]); split_f16(v.y, H.a[1], L.a[1]);
    split_f16(v.z, H.a[2], L.a[2]); split_f16(v.w, H.a[3], L.a[3]);
    *(uint2*)(g_xh + i * 4) = H.u;
    *(uint2*)(g_xl + i * 4) = L.u;
}

__global__ __launch_bounds__(256) void wsplit_kernel(const float* __restrict__ wt) {
    __shared__ float tile[32][33];
    const int h = blockIdx.z, k0 = blockIdx.y * 32, n0 = blockIdx.x * 32;
    const int tx = threadIdx.x, ty = threadIdx.y;
#pragma unroll
    for (int j = 0; j < 4; ++j)
        tile[ty + 8 * j][tx] = wt[((size_t)h * 1024 + k0 + ty + 8 * j) * 1024 + n0 + tx];
    __syncthreads();
#pragma unroll
    for (int j = 0; j < 4; ++j) {
        const int nn = ty + 8 * j, kk = tx;
        g_wth[((size_t)h * 1024 + n0 + nn) * 1024 + k0 + kk] =
            __float2half_rn(tile[kk][nn]);
    }
}

// ---------------- scores: persistent row-tile, loops all 16 col tiles ----------------
__global__ __launch_bounds__(256, 2) void scores_hmma() {
    extern __shared__ char smraw[];
    const uint32_t sb = smem_u32(smraw);
    const int tid = threadIdx.x, lane = tid & 31, warp = tid >> 5;
    const int wm = (warp & 3) * 32, wn = (warp >> 2) * 64;
    __shared__ float rsum[128];

    const int bh = blockIdx.y, b = bh >> 4, hh = bh & 15;
    const int row0 = blockIdx.x * 128;

    const size_t ab = (size_t)(b * TSEQ + row0) * CEMB + hh * 64;
    const size_t bbase = (size_t)(b * TSEQ) * CEMB + hh * 64;

    copy128(sb, g_xh + ab, CEMB, tid);
    copy128(sb + SUBK, g_xh + ab + 32, CEMB, tid);
    copy128(sb + 2 * SUBK, g_xl + ab, CEMB, tid);
    copy128(sb + 3 * SUBK, g_xl + ab + 32, CEMB, tid);
    auto loadB = [&](int ct) {
        const uint32_t dst = sb + A_FULL + (uint32_t)(ct % 3) * B_BUF;
        const __half* src = g_xh + bbase + (size_t)(ct * 128) * CEMB;
        copy128(dst, src, CEMB, tid);
        copy128(dst + SUBK, src + 32, CEMB, tid);
    };
    loadB(0); cp_commit();
    loadB(1); cp_commit();
    if (tid < 128) rsum[tid] = 0.f;

    const int g = lane >> 2, t2 = (lane & 3) * 2;
    float rs[2][2];
    rs[0][0] = rs[0][1] = rs[1][0] = rs[1][1] = 0.f;

    for (int ct = 0; ct < 16; ++ct) {
        cp_wait<1>();
        __syncthreads();
        if (ct + 2 < 16) loadB(ct + 2);
        cp_commit();

        float acc[2][8][4];
#pragma unroll
        for (int i = 0; i < 2; ++i)
#pragma unroll
            for (int j = 0; j < 8; ++j)
#pragma unroll
                for (int q = 0; q < 4; ++q) acc[i][j][q] = 0.f;

        const uint32_t bB = sb + A_FULL + (uint32_t)(ct % 3) * B_BUF;
        compute_sc32(sb, bB, wm, wn, lane, acc);
        compute_sc32(sb + SUBK, bB + SUBK, wm, wn, lane, acc);

        __half* Ep = g_E + ((size_t)bh * TSEQ + row0) * TSEQ + ct * 128;
#pragma unroll
        for (int mt = 0; mt < 2; ++mt)
#pragma unroll
            for (int nt = 0; nt < 8; ++nt) {
                const int r = wm + mt * 16 + g, c = wn + nt * 8 + t2;
                const float e0 = __expf(acc[mt][nt][0] * 0.125f - 8.0f);
                const float e1 = __expf(acc[mt][nt][1] * 0.125f - 8.0f);
                const float e2 = __expf(acc[mt][nt][2] * 0.125f - 8.0f);
                const float e3 = __expf(acc[mt][nt][3] * 0.125f - 8.0f);
                rs[mt][0] += e0 + e1;
                rs[mt][1] += e2 + e3;
                *(uint32_t*)(Ep + (size_t)r * TSEQ + c) =
                    pack2h(__float2half_rn(e0), __float2half_rn(e1));
                *(uint32_t*)(Ep + (size_t)(r + 8) * TSEQ + c) =
                    pack2h(__float2half_rn(e2), __float2half_rn(e3));
            }
    }

#pragma unroll
    for (int mt = 0; mt < 2; ++mt) {
        atomicAdd(&rsum[wm + mt * 16 + g], rs[mt][0]);
        atomicAdd(&rsum[wm + mt * 16 + g + 8], rs[mt][1]);
    }
    __syncthreads();
    if (tid < 128) {
        const float s = rsum[tid];
        const size_t idx = (size_t)bh * TSEQ + row0 + tid;
        g_rowsum[idx] = s;
        g_invf[idx] = 1.0f / s;
    }
}

// ---------------- Z[h] = X @ W_h (K=1024), 128x128 tile, 2 CTA/SM ----------------
__global__ __launch_bounds__(256, 2) void z_hmma() {
    extern __shared__ char smraw[];
    const uint32_t sb = smem_u32(smraw);
    const int tid = threadIdx.x, lane = tid & 31, warp = tid >> 5;
    const int wm = (warp & 3) * 32, wn = (warp >> 2) * 64;
    const int hh = blockIdx.z;
    const int row0 = blockIdx.y * 128, col0 = blockIdx.x * 128;

    float acc[2][8][4];
#pragma unroll
    for (int i = 0; i < 2; ++i)
#pragma unroll
        for (int j = 0; j < 8; ++j)
#pragma unroll
            for (int q = 0; q < 4; ++q) acc[i][j][q] = 0.f;

    const size_t ab = (size_t)row0 * CEMB;
    const size_t bb = ((size_t)hh * 1024 + col0) * 1024;
    const int NP = 16;                           // 16 pairs of k32 = K 1024

    auto loadP = [&](int t) {                    // stage pair: A0 B0 A1 B1 @ 10240 each
        const uint32_t st = sb + (uint32_t)(t & 1) * PAIR_Z;
        copy128(st, g_xh + ab + (2 * t) * 32, CEMB, tid);
        copy128(st + SUBK, g_wth + bb + (2 * t) * 32, 1024, tid);
        copy128(st + 2 * SUBK, g_xh + ab + (2 * t + 1) * 32, CEMB, tid);
        copy128(st + 3 * SUBK, g_wth + bb + (2 * t + 1) * 32, 1024, tid);
    };
    loadP(0); cp_commit();
    for (int pt = 0; pt < NP; ++pt) {
        cp_wait<0>();
        __syncthreads();
        if (pt + 1 < NP) loadP(pt + 1);
        cp_commit();
        const uint32_t st = sb + (uint32_t)(pt & 1) * PAIR_Z;
        compute_z32(st, wm, wn, lane, acc);          // A@st,      B@st+10240
        compute_z32(st + 2 * SUBK, wm, wn, lane, acc);  // A@+20480, B@+30720
    }

    const int g = lane >> 2, t2 = (lane & 3) * 2;
#pragma unroll
    for (int mt = 0; mt < 2; ++mt)
#pragma unroll
        for (int nt = 0; nt < 8; ++nt) {
            const int r = row0 + wm + mt * 16 + g;
            const int c = col0 + wn + nt * 8 + t2;
            const size_t o0 = ((size_t)hh * 4096 + r) * 1024 + c;
            *(uint32_t*)(g_Zh + o0) =
                pack2h(__float2half_rn(acc[mt][nt][0]), __float2half_rn(acc[mt][nt][1]));
            *(uint32_t*)(g_Zh + o0 + 8 * 1024) =
                pack2h(__float2half_rn(acc[mt][nt][2]), __float2half_rn(acc[mt][nt][3]));
        }
}

// ---------------- out[b] = sum_h inv_h * (E_h @ Z[h,b]), head-boundary rescale ----------------
__global__ __launch_bounds__(256, 1) void out_hmma(float* __restrict__ out) {
    extern __shared__ char smraw[];
    const uint32_t sb = smem_u32(smraw);
    const int tid = threadIdx.x, lane = tid & 31, warp = tid >> 5;
    const int wm = (warp & 1) * 64, wn = (warp >> 1) * 64;
    float acc[4][8][4];
#pragma unroll
    for (int i = 0; i < 4; ++i)
#pragma unroll
        for (int j = 0; j < 8; ++j)
#pragma unroll
            for (int q = 0; q < 4; ++q) acc[i][j][q] = 0.f;

    const int b = blockIdx.z;
    const int row0 = blockIdx.y * 128, col0 = blockIdx.x * 256;
    const int g = lane >> 2;

    const size_t arow = ((size_t)(b * 16) * TSEQ + row0) * TSEQ;
    const int NQ = 256;                          // 256 quads of k32 ; head = qt>>4
    auto loadQ = [&](int t) {
        const uint32_t st = sb + (uint32_t)(t & 1) * QUAD_O;
#pragma unroll
        for (int j = 0; j < 4; ++j) {
            const int u = 4 * t + j;
            const int hh = u >> 6, s0 = (u & 63) * 32;
            const size_t ap = arow + (size_t)hh * TSEQ * TSEQ + s0;
            const size_t bp = ((size_t)hh * 4096 + b * TSEQ + s0) * 1024 + col0;
            const uint32_t ss = st + (uint32_t)j * SUB_O;
            copy128(ss, g_E + ap, TSEQ, tid);
            copyBS1(ss + ZO_BOFF, g_Zh + bp, 1024, tid);
        }
    };
    loadQ(0); cp_commit();

    float inv_cur[4][2];
    int curh = -1;
    for (int qt = 0; qt < NQ; ++qt) {
        const int hh = qt >> 4;
        if (hh != curh) {
            const float* invp = g_invf + ((size_t)(b * 16 + hh)) * TSEQ + row0;
            const float* rsp = g_rowsum + ((size_t)(b * 16 + hh)) * TSEQ + row0;
            if (curh >= 0) {
#pragma unroll
                for (int mt = 0; mt < 4; ++mt) {
                    const int r = wm + mt * 16 + g;
                    const float r0 = inv_cur[mt][0] * rsp[r];
                    const float r1 = inv_cur[mt][1] * rsp[r + 8];
#pragma unroll
                    for (int nt = 0; nt < 8; ++nt) {
                        acc[mt][nt][0] *= r0; acc[mt][nt][1] *= r0;
                        acc[mt][nt][2] *= r1; acc[mt][nt][3] *= r1;
                    }
                }
            }
#pragma unroll
            for (int mt = 0; mt < 4; ++mt) {
                const int r = wm + mt * 16 + g;
                inv_cur[mt][0] = invp[r];
                inv_cur[mt][1] = invp[r + 8];
            }
            curh = hh;
        }
        cp_wait<0>();
        __syncthreads();
        if (qt + 1 < NQ) loadQ(qt + 1);
        cp_commit();
        const uint32_t st = sb + (uint32_t)(qt & 1) * QUAD_O;
        compute_o(st, wm, wn, lane, acc);
        compute_o(st + SUB_O, wm, wn, lane, acc);
        compute_o(st + 2 * SUB_O, wm, wn, lane, acc);
        compute_o(st + 3 * SUB_O, wm, wn, lane, acc);
    }

    const int t2 = (lane & 3) * 2;
    float* Op = out + ((size_t)(b * TSEQ + row0)) * CEMB + col0;
#pragma unroll
    for (int mt = 0; mt < 4; ++mt)
#pragma unroll
        for (int nt = 0; nt < 8; ++nt) {
            const int r = wm + mt * 16 + g, c = wn + nt * 8 + t2;
            *(float2*)(Op + (size_t)r * CEMB + c) =
                make_float2(acc[mt][nt][0] * inv_cur[mt][0], acc[mt][nt][1] * inv_cur[mt][0]);
            *(float2*)(Op + (size_t)(r + 8) * CEMB + c) =
                make_float2(acc[mt][nt][2] * inv_cur[mt][1], acc[mt][nt][3] * inv_cur[mt][1]);
        }
}

// ---------------------------------------------------------------------------
extern "C" void kernel_launch(void* const* d_in, const int* in_sizes, int n_in,
                              void* d_out, int out_size) {
    const float* x  = (const float*)d_in[0];   // [2,2048,1024]
    const float* wt = (const float*)d_in[1];   // [16384,1024]
    float* out = (float*)d_out;

    cudaFuncSetAttribute(scores_hmma, cudaFuncAttributeMaxDynamicSharedMemorySize, SMEM_SC);
    cudaFuncSetAttribute(z_hmma,      cudaFuncAttributeMaxDynamicSharedMemorySize, SMEM_Z);
    cudaFuncSetAttribute(out_hmma,    cudaFuncAttributeMaxDynamicSharedMemorySize, SMEM_O);

    xsplit_kernel<<<4096, 256>>>(x);
    wsplit_kernel<<<dim3(32, 32, 16), dim3(32, 8)>>>(wt);
    scores_hmma<<<dim3(16, 32), 256, SMEM_SC>>>();
    z_hmma<<<dim3(8, 32, 16), 256, SMEM_Z>>>();
    out_hmma<<<dim3(4, 16, 2), 256, SMEM_O>>>(out);
}